// round 4
// baseline (speedup 1.0000x reference)
#include <cuda_runtime.h>

// R2Ntab: out[b] = (# rules r with h[b,r] > 0.999999) * [w_or>0] + b_or,
// h[b,r] = x_b . rw_r + b_and[r] - relu(rw_r).sum(), rw = w_and masked by
// w_cancel<0 columns. x binary => pass <=> 256-bit pattern match
// (x_bits & care_r) == pos_r (tiny weights -> don't-care or exact fallback).

#define FDIM 256
#define RDIM 128

// Bit layout: feature f = h*128 + 4*j + c -> word w = h*4 + c, bit j.

__device__ unsigned g_pos[8][RDIM];
__device__ unsigned g_care[8][RDIM];
__device__ float    g_thresh[RDIM];
__device__ float    g_rw[RDIM * FDIM];
__device__ int      g_exact_flag[RDIM];

// ---------------------------------------------------------------------------
// Prep: one warp per rule.
// ---------------------------------------------------------------------------
__global__ void prep_kernel(const float* __restrict__ wc,
                            const float* __restrict__ wa,
                            const float* __restrict__ ba,
                            const float* __restrict__ wo) {
    int gt   = blockIdx.x * blockDim.x + threadIdx.x;
    int r    = gt >> 5;
    int lane = gt & 31;
    if (r >= RDIM) return;

    float eps     = ba[r] - 0.999999f;
    bool  include = wo[r] > 0.0f;

    float relu_sum = 0.f, sum_tiny = 0.f;
    unsigned pos[8], care[8];
#pragma unroll
    for (int h = 0; h < 2; h++) {
#pragma unroll
        for (int c = 0; c < 4; c++) {
            int   w  = h * 4 + c;
            int   f  = h * 128 + 4 * lane + c;
            float wv = (wc[f] < 0.f) ? 0.f : wa[r * FDIM + f];
            g_rw[r * FDIM + f] = wv;
            relu_sum += fmaxf(wv, 0.f);
            float aw   = fabsf(wv);
            bool  must = (aw >= eps);
            if (!must) sum_tiny += aw;
            pos[w]  = __ballot_sync(0xffffffffu, must && (wv > 0.f));
            care[w] = __ballot_sync(0xffffffffu, must && (wv != 0.f));
        }
    }
#pragma unroll
    for (int o = 16; o; o >>= 1) {
        relu_sum += __shfl_xor_sync(0xffffffffu, relu_sum, o);
        sum_tiny += __shfl_xor_sync(0xffffffffu, sum_tiny, o);
    }

    bool afalse = (!include) || (eps <= 0.f);
    bool exact  = (!afalse) && (sum_tiny >= eps);
    if (afalse || exact) {
#pragma unroll
        for (int w = 0; w < 8; w++) { pos[w] = 0u; care[w] = 0u; }
        pos[0] = 0xFFFFFFFFu;   // never matches
    }
    if (lane == 0) {
        g_thresh[r]     = relu_sum - eps;
        g_exact_flag[r] = exact ? 1 : 0;
#pragma unroll
        for (int w = 0; w < 8; w++) { g_pos[w][r] = pos[w]; g_care[w][r] = care[w]; }
    }
}

// x values are exactly 0.0f / 1.0f -> exact integer pack via FFMA chain.
__device__ __forceinline__ unsigned pack_bits(float4 a, float4 b) {
    float s = a.x;
    s = fmaf(2.f,   a.y, s);
    s = fmaf(4.f,   a.z, s);
    s = fmaf(8.f,   a.w, s);
    s = fmaf(16.f,  b.x, s);
    s = fmaf(32.f,  b.y, s);
    s = fmaf(64.f,  b.z, s);
    s = fmaf(128.f, b.w, s);
    return (unsigned)s;
}

// ---------------------------------------------------------------------------
// Main: warp per row, 2 rows per chunk, software-pipelined prefetch so loads
// are continuously in flight. Fast path per row: 2 ballots + 4 LOP3/ISETP.
// ---------------------------------------------------------------------------
__global__ void __launch_bounds__(256, 5)
main_kernel(const float* __restrict__ x,
            const float* __restrict__ bor,
            float* __restrict__ out, int B) {
    __shared__ unsigned s_pos[8][RDIM];
    __shared__ unsigned s_care[8][RDIM];
    __shared__ int s_nx;
    __shared__ int s_xr[RDIM];

    int tid = threadIdx.x;
    if (tid == 0) s_nx = 0;
    __syncthreads();
    for (int i = tid; i < 8 * RDIM; i += blockDim.x) {
        (&s_pos[0][0])[i]  = (&g_pos[0][0])[i];
        (&s_care[0][0])[i] = (&g_care[0][0])[i];
    }
    if (tid < RDIM && g_exact_flag[tid]) {
        int i = atomicAdd(&s_nx, 1);
        s_xr[i] = tid;
    }
    __syncthreads();

    const int   lane = tid & 31;
    const int   nx   = s_nx;
    const float b0   = bor[0];

    unsigned p0[4], c0[4];
#pragma unroll
    for (int k = 0; k < 4; k++) {
        p0[k] = s_pos[0][lane + 32 * k];
        c0[k] = s_care[0][lane + 32 * k];
    }

    const int gw = blockIdx.x * (blockDim.x >> 5) + (tid >> 5);
    const int nw = gridDim.x * (blockDim.x >> 5);
    const int nchunks = B >> 1;               // 2 rows per chunk

    // ---- full check for one row given its packed per-lane bits ----
    auto process_row = [&](unsigned bits, int row) {
        unsigned xw0 = __ballot_sync(0xffffffffu, bits & 1u);
        bool cand = false;
#pragma unroll
        for (int k = 0; k < 4; k++)
            cand |= (((xw0 & c0[k]) ^ p0[k]) == 0u);
        unsigned any = __ballot_sync(0xffffffffu, cand);

        if (any == 0u && nx == 0) {                 // warp-uniform, ~always
            if (lane == 0) out[row] = b0;
            return;
        }
        // Rare path.
        unsigned xw[8];
        xw[0] = xw0;
#pragma unroll
        for (int w = 1; w < 8; w++)
            xw[w] = __ballot_sync(0xffffffffu, (bits >> w) & 1u);
        int cnt = 0;
#pragma unroll
        for (int k = 0; k < 4; k++) {
            int r = lane + 32 * k;
            unsigned acc = (xw0 & c0[k]) ^ p0[k];
            if (acc == 0u) {
#pragma unroll
                for (int w = 1; w < 8; w++)
                    acc |= (xw[w] & s_care[w][r]) ^ s_pos[w][r];
                if (acc == 0u) cnt++;
            }
        }
        for (int e = 0; e < nx; e++) {              // exact fp32 fallback
            int r = s_xr[e];
            float s = 0.f;
#pragma unroll
            for (int w = 0; w < 8; w++) {
                if ((xw[w] >> lane) & 1u) {
                    int h = w >> 2, c = w & 3;
                    s += g_rw[r * FDIM + h * 128 + 4 * lane + c];
                }
            }
#pragma unroll
            for (int o = 16; o; o >>= 1)
                s += __shfl_xor_sync(0xffffffffu, s, o);
            if (lane == 0 && s > g_thresh[r]) cnt++;
        }
#pragma unroll
        for (int o = 16; o; o >>= 1)
            cnt += __shfl_xor_sync(0xffffffffu, cnt, o);
        if (lane == 0) out[row] = (float)cnt + b0;
    };

    // ---- software pipeline: prefetch chunk ch+nw while processing ch ----
    float4 a0, b0v, a1, b1v;
    int ch = gw;
    if (ch < nchunks) {
        const float4* xr0 = (const float4*)(x + (size_t)(2 * ch)     * FDIM);
        const float4* xr1 = (const float4*)(x + (size_t)(2 * ch + 1) * FDIM);
        a0  = __ldcs(&xr0[lane]);  b0v = __ldcs(&xr0[lane + 32]);
        a1  = __ldcs(&xr1[lane]);  b1v = __ldcs(&xr1[lane + 32]);
    }
    while (ch < nchunks) {
        unsigned bits0 = pack_bits(a0, b0v);
        unsigned bits1 = pack_bits(a1, b1v);
        int next = ch + nw;
        if (next < nchunks) {                       // prefetch next chunk
            const float4* xr0 = (const float4*)(x + (size_t)(2 * next)     * FDIM);
            const float4* xr1 = (const float4*)(x + (size_t)(2 * next + 1) * FDIM);
            a0  = __ldcs(&xr0[lane]);  b0v = __ldcs(&xr0[lane + 32]);
            a1  = __ldcs(&xr1[lane]);  b1v = __ldcs(&xr1[lane + 32]);
        }
        process_row(bits0, 2 * ch);
        process_row(bits1, 2 * ch + 1);
        ch = next;
    }

    // Tail rows (B odd; not hit for B=131072).
    for (int row = (nchunks << 1) + gw; row < B; row += nw) {
        const float4* xr = (const float4*)(x + (size_t)row * FDIM);
        float4 a = __ldcs(&xr[lane]);
        float4 b = __ldcs(&xr[lane + 32]);
        process_row(pack_bits(a, b), row);
    }
}

extern "C" void kernel_launch(void* const* d_in, const int* in_sizes, int n_in,
                              void* d_out, int out_size) {
    const float* x  = (const float*)d_in[0];   // [B, 256] binary
    const float* wc = (const float*)d_in[1];   // [256]
    const float* wa = (const float*)d_in[2];   // [128, 256]
    const float* ba = (const float*)d_in[3];   // [128]
    const float* wo = (const float*)d_in[4];   // [1, 128]
    const float* bo = (const float*)d_in[5];   // [1]
    float* out = (float*)d_out;

    int B = in_sizes[0] / FDIM;

    prep_kernel<<<4, 1024>>>(wc, wa, ba, wo);      // 128 warps, 1 per rule
    main_kernel<<<740, 256>>>(x, bo, out, B);      // 5 blocks/SM, persistent
}

// round 5
// speedup vs baseline: 1.0510x; 1.0510x over previous
#include <cuda_runtime.h>

// R2Ntab: out[b] = (# rules r with h[b,r] > 0.999999) * [w_or>0] + b_or,
// h[b,r] = x_b . rw_r + b_and[r] - relu(rw_r).sum(), rw = w_and masked by
// w_cancel<0 columns. x binary => pass <=> 256-bit pattern match
// (x_bits & care_r) == pos_r (tiny weights -> don't-care or exact fallback).
//
// R5: bulk-async (UBLKCP) SMEM pipeline. In-flight bytes live in SMEM, not
// registers, breaking the RF-bound MLP ceiling that capped DRAM at ~65%.

#define FDIM 256
#define RDIM 128
#define TILE_ROWS 32
#define ROW_BYTES (FDIM * 4)            // 1024
#define TILE_BYTES (TILE_ROWS * ROW_BYTES)   // 32768
#define NSTAGES 3
#define NTHREADS 256
#define NBLOCKS 296

__device__ unsigned g_pos[8][RDIM];
__device__ unsigned g_care[8][RDIM];
__device__ float    g_thresh[RDIM];
__device__ float    g_rw[RDIM * FDIM];
__device__ int      g_exact_flag[RDIM];

// ---------------------------------------------------------------------------
// PTX helpers (inline; single-file build)
// ---------------------------------------------------------------------------
__device__ __forceinline__ unsigned smem_u32(const void* p) {
    unsigned a;
    asm("{ .reg .u64 t; cvta.to.shared.u64 t, %1; cvt.u32.u64 %0, t; }"
        : "=r"(a) : "l"(p));
    return a;
}
#define MBAR_INIT(addr, cnt) \
    asm volatile("mbarrier.init.shared.b64 [%0], %1;" :: "r"(addr), "r"(cnt) : "memory")
#define MBAR_EXPECT_TX(addr, bytes) \
    asm volatile("mbarrier.arrive.expect_tx.shared.b64 _, [%0], %1;" \
                 :: "r"(addr), "r"(bytes) : "memory")
#define BULK_G2S(dst_smem, src_gmem, bytes, mbar) \
    asm volatile("cp.async.bulk.shared::cta.global.mbarrier::complete_tx::bytes " \
                 "[%0], [%1], %2, [%3];" \
                 :: "r"(dst_smem), "l"(src_gmem), "r"(bytes), "r"(mbar) : "memory")
__device__ __forceinline__ void mbar_wait(unsigned mbar, unsigned parity) {
    unsigned done;
    asm volatile(
        "{\n\t.reg .pred p;\n\t"
        "mbarrier.try_wait.parity.acquire.cta.shared::cta.b64 p, [%1], %2;\n\t"
        "selp.b32 %0, 1, 0, p;\n\t}"
        : "=r"(done) : "r"(mbar), "r"(parity) : "memory");
    if (!done) {
        asm volatile(
            "{\n\t.reg .pred P1;\n\t"
            "WL_%=:\n\t"
            "mbarrier.try_wait.parity.acquire.cta.shared::cta.b64 P1, [%0], %1, 0x989680;\n\t"
            "@P1 bra.uni WD_%=;\n\t"
            "bra.uni WL_%=;\n\t"
            "WD_%=:\n\t}"
            :: "r"(mbar), "r"(parity) : "memory");
    }
}

// ---------------------------------------------------------------------------
// Prep: one warp per rule.
// ---------------------------------------------------------------------------
__global__ void prep_kernel(const float* __restrict__ wc,
                            const float* __restrict__ wa,
                            const float* __restrict__ ba,
                            const float* __restrict__ wo) {
    int gt   = blockIdx.x * blockDim.x + threadIdx.x;
    int r    = gt >> 5;
    int lane = gt & 31;
    if (r >= RDIM) return;

    float eps     = ba[r] - 0.999999f;
    bool  include = wo[r] > 0.0f;

    float relu_sum = 0.f, sum_tiny = 0.f;
    unsigned pos[8], care[8];
#pragma unroll
    for (int h = 0; h < 2; h++) {
#pragma unroll
        for (int c = 0; c < 4; c++) {
            int   w  = h * 4 + c;
            int   f  = h * 128 + 4 * lane + c;
            float wv = (wc[f] < 0.f) ? 0.f : wa[r * FDIM + f];
            g_rw[r * FDIM + f] = wv;
            relu_sum += fmaxf(wv, 0.f);
            float aw   = fabsf(wv);
            bool  must = (aw >= eps);
            if (!must) sum_tiny += aw;
            pos[w]  = __ballot_sync(0xffffffffu, must && (wv > 0.f));
            care[w] = __ballot_sync(0xffffffffu, must && (wv != 0.f));
        }
    }
#pragma unroll
    for (int o = 16; o; o >>= 1) {
        relu_sum += __shfl_xor_sync(0xffffffffu, relu_sum, o);
        sum_tiny += __shfl_xor_sync(0xffffffffu, sum_tiny, o);
    }

    bool afalse = (!include) || (eps <= 0.f);
    bool exact  = (!afalse) && (sum_tiny >= eps);
    if (afalse || exact) {
#pragma unroll
        for (int w = 0; w < 8; w++) { pos[w] = 0u; care[w] = 0u; }
        pos[0] = 0xFFFFFFFFu;   // never matches
    }
    if (lane == 0) {
        g_thresh[r]     = relu_sum - eps;
        g_exact_flag[r] = exact ? 1 : 0;
#pragma unroll
        for (int w = 0; w < 8; w++) { g_pos[w][r] = pos[w]; g_care[w][r] = care[w]; }
    }
}

// x entries are exactly 0.0f / 1.0f -> exact integer pack via FFMA chain.
__device__ __forceinline__ unsigned pack_bits(float4 a, float4 b) {
    float s = a.x;
    s = fmaf(2.f,   a.y, s);
    s = fmaf(4.f,   a.z, s);
    s = fmaf(8.f,   a.w, s);
    s = fmaf(16.f,  b.x, s);
    s = fmaf(32.f,  b.y, s);
    s = fmaf(64.f,  b.z, s);
    s = fmaf(128.f, b.w, s);
    return (unsigned)s;
}

// ---------------------------------------------------------------------------
// Main: bulk-copy 32KB tiles through a 3-stage SMEM ring; 8 warps consume
// 4 rows each per tile. Fast path per row: 2 LDS.128 + pack + 2 ballots.
// ---------------------------------------------------------------------------
__global__ void __launch_bounds__(NTHREADS, 2)
main_kernel(const float* __restrict__ x,
            const float* __restrict__ bor,
            float* __restrict__ out, int B) {
    extern __shared__ __align__(128) char dsmem[];      // NSTAGES * TILE_BYTES
    __shared__ unsigned s_pos[8][RDIM];
    __shared__ unsigned s_care[8][RDIM];
    __shared__ int s_nx;
    __shared__ int s_xr[RDIM];
    __shared__ __align__(8) unsigned long long s_mbar[NSTAGES];

    const int tid = threadIdx.x;
    if (tid == 0) {
        s_nx = 0;
#pragma unroll
        for (int s = 0; s < NSTAGES; s++)
            MBAR_INIT(smem_u32(&s_mbar[s]), 1);
    }
    __syncthreads();
    for (int i = tid; i < 8 * RDIM; i += NTHREADS) {
        (&s_pos[0][0])[i]  = (&g_pos[0][0])[i];
        (&s_care[0][0])[i] = (&g_care[0][0])[i];
    }
    if (tid < RDIM && g_exact_flag[tid]) {
        int i = atomicAdd(&s_nx, 1);
        s_xr[i] = tid;
    }
    __syncthreads();

    const int   lane = tid & 31;
    const int   wid  = tid >> 5;
    const int   nx   = s_nx;
    const float b0   = bor[0];

    unsigned p0[4], c0[4];
#pragma unroll
    for (int k = 0; k < 4; k++) {
        p0[k] = s_pos[0][lane + 32 * k];
        c0[k] = s_care[0][lane + 32 * k];
    }

    const int ntiles = (B + TILE_ROWS - 1) / TILE_ROWS;
    // Block's tiles: bid, bid+grid, ... ; local index t counts them.
    int nt_blk = 0;
    for (int t = blockIdx.x; t < ntiles; t += gridDim.x) nt_blk++;

    auto tile_of = [&](int t_local) { return blockIdx.x + t_local * gridDim.x; };
    auto rows_of = [&](int tile)    { int r = B - tile * TILE_ROWS;
                                      return r < TILE_ROWS ? r : TILE_ROWS; };

    // Prologue: fill the pipeline.
    if (tid == 0) {
        for (int i = 0; i < NSTAGES && i < nt_blk; i++) {
            int tile = tile_of(i);
            unsigned bytes = (unsigned)rows_of(tile) * ROW_BYTES;
            unsigned mb = smem_u32(&s_mbar[i]);
            MBAR_EXPECT_TX(mb, bytes);
            BULK_G2S(smem_u32(dsmem + i * TILE_BYTES),
                     (const void*)(x + (size_t)tile * TILE_ROWS * FDIM),
                     bytes, mb);
        }
    }

    for (int t = 0; t < nt_blk; t++) {
        const int s    = t % NSTAGES;
        const unsigned ph = (unsigned)((t / NSTAGES) & 1);
        const int tile = tile_of(t);
        const int nrows = rows_of(tile);
        const int rowbase = tile * TILE_ROWS;

        mbar_wait(smem_u32(&s_mbar[s]), ph);

        const char* tp = dsmem + s * TILE_BYTES;
#pragma unroll
        for (int u = 0; u < 4; u++) {
            int rrow = wid * 4 + u;
            if (rrow >= nrows) break;
            const float4* xr = (const float4*)(tp + rrow * ROW_BYTES);
            float4 a = xr[lane];
            float4 b = xr[lane + 32];
            unsigned bits = pack_bits(a, b);
            int row = rowbase + rrow;

            unsigned xw0 = __ballot_sync(0xffffffffu, bits & 1u);
            bool cand = false;
#pragma unroll
            for (int k = 0; k < 4; k++)
                cand |= (((xw0 & c0[k]) ^ p0[k]) == 0u);
            unsigned any = __ballot_sync(0xffffffffu, cand);

            if (any == 0u && nx == 0) {              // warp-uniform, ~always
                if (lane == 0) out[row] = b0;
                continue;
            }
            // Rare path: remaining 7 ballots + full checks.
            unsigned xw[8];
            xw[0] = xw0;
#pragma unroll
            for (int w = 1; w < 8; w++)
                xw[w] = __ballot_sync(0xffffffffu, (bits >> w) & 1u);
            int cnt = 0;
#pragma unroll
            for (int k = 0; k < 4; k++) {
                int r = lane + 32 * k;
                unsigned acc = (xw0 & c0[k]) ^ p0[k];
                if (acc == 0u) {
#pragma unroll
                    for (int w = 1; w < 8; w++)
                        acc |= (xw[w] & s_care[w][r]) ^ s_pos[w][r];
                    if (acc == 0u) cnt++;
                }
            }
            for (int e = 0; e < nx; e++) {           // exact fp32 fallback
                int r = s_xr[e];
                float sum = 0.f;
#pragma unroll
                for (int w = 0; w < 8; w++) {
                    if ((xw[w] >> lane) & 1u) {
                        int h = w >> 2, c = w & 3;
                        sum += g_rw[r * FDIM + h * 128 + 4 * lane + c];
                    }
                }
#pragma unroll
                for (int o = 16; o; o >>= 1)
                    sum += __shfl_xor_sync(0xffffffffu, sum, o);
                if (lane == 0 && sum > g_thresh[r]) cnt++;
            }
#pragma unroll
            for (int o = 16; o; o >>= 1)
                cnt += __shfl_xor_sync(0xffffffffu, cnt, o);
            if (lane == 0) out[row] = (float)cnt + b0;
        }

        __syncthreads();                             // all reads of stage s done
        if (tid == 0 && t + NSTAGES < nt_blk) {      // refill stage s
            int ntile = tile_of(t + NSTAGES);
            unsigned bytes = (unsigned)rows_of(ntile) * ROW_BYTES;
            unsigned mb = smem_u32(&s_mbar[s]);
            MBAR_EXPECT_TX(mb, bytes);
            BULK_G2S(smem_u32(dsmem + s * TILE_BYTES),
                     (const void*)(x + (size_t)ntile * TILE_ROWS * FDIM),
                     bytes, mb);
        }
    }
}

extern "C" void kernel_launch(void* const* d_in, const int* in_sizes, int n_in,
                              void* d_out, int out_size) {
    const float* x  = (const float*)d_in[0];   // [B, 256] binary
    const float* wc = (const float*)d_in[1];   // [256]
    const float* wa = (const float*)d_in[2];   // [128, 256]
    const float* ba = (const float*)d_in[3];   // [128]
    const float* wo = (const float*)d_in[4];   // [1, 128]
    const float* bo = (const float*)d_in[5];   // [1]
    float* out = (float*)d_out;

    int B = in_sizes[0] / FDIM;

    static int attr_set = 0;
    if (!attr_set) {
        cudaFuncSetAttribute(main_kernel,
                             cudaFuncAttributeMaxDynamicSharedMemorySize,
                             NSTAGES * TILE_BYTES);
        attr_set = 1;
    }

    prep_kernel<<<4, 1024>>>(wc, wa, ba, wo);
    main_kernel<<<NBLOCKS, NTHREADS, NSTAGES * TILE_BYTES>>>(x, bo, out, B);
}